// round 1
// baseline (speedup 1.0000x reference)
#include <cuda_runtime.h>
#include <cuda_bf16.h>

#define HH 64
#define WARPS_PER_BLOCK 8
#define THREADS (WARPS_PER_BLOCK * 32)
#define GRID_BLOCKS 2048

// tanh and its first three derivatives
__device__ __forceinline__ void tanh_derivs(float z, float& f, float& f1, float& f2, float& f3) {
    f  = tanhf(z);
    f1 = 1.0f - f * f;          // f'
    f2 = -2.0f * f * f1;        // f''
    f3 = -2.0f * (f1 * f1 + f * f2);  // f'''
}

// Faa di Bruno: h = tanh(z(p,t)) jet composition, accumulate w3 * h-jet into acc.
// jet order: [0]=val [1]=p [2]=t [3]=pp [4]=pt [5]=tt [6]=ppp [7]=ppt [8]=ptt [9]=ttt
__device__ __forceinline__ void compose_acc(const float* z, float w3, float* acc) {
    float f, f1, f2, f3;
    tanh_derivs(z[0], f, f1, f2, f3);
    float zp = z[1], zt = z[2], zpp = z[3], zpt = z[4], ztt = z[5];
    float zppp = z[6], zppt = z[7], zptt = z[8], zttt = z[9];
    acc[0] = fmaf(w3, f, acc[0]);
    acc[1] = fmaf(w3, f1 * zp, acc[1]);
    acc[2] = fmaf(w3, f1 * zt, acc[2]);
    acc[3] = fmaf(w3, fmaf(f2, zp * zp, f1 * zpp), acc[3]);
    acc[4] = fmaf(w3, fmaf(f2, zp * zt, f1 * zpt), acc[4]);
    acc[5] = fmaf(w3, fmaf(f2, zt * zt, f1 * ztt), acc[5]);
    acc[6] = fmaf(w3, f3 * zp * zp * zp + 3.0f * f2 * zp * zpp + f1 * zppp, acc[6]);
    acc[7] = fmaf(w3, f3 * zp * zp * zt + f2 * (zpp * zt + 2.0f * zp * zpt) + f1 * zppt, acc[7]);
    acc[8] = fmaf(w3, f3 * zp * zt * zt + f2 * (ztt * zp + 2.0f * zt * zpt) + f1 * zptt, acc[8]);
    acc[9] = fmaf(w3, f3 * zt * zt * zt + 3.0f * f2 * zt * ztt + f1 * zttt, acc[9]);
}

__global__ __launch_bounds__(THREADS) void pinn_flow_kernel(
    const float* __restrict__ phi, const float* __restrict__ theta,
    const float* __restrict__ radius, const float* __restrict__ hth,
    const float* __restrict__ hph, const float* __restrict__ brr,
    const float* __restrict__ W1, const float* __restrict__ b1,
    const float* __restrict__ W2, const float* __restrict__ b2,
    const float* __restrict__ W3, const float* __restrict__ b3,
    float* __restrict__ out, int n)
{
    __shared__ float sW2[HH][HH];                    // [j][k], 16 KB
    __shared__ float sL1[HH][12];                    // a,b,aa,ab,bb,aaa,aab,abb,bbb,b1 (pad 12)
    __shared__ float sB2[HH];
    __shared__ float sW3[HH];
    __shared__ float sV[WARPS_PER_BLOCK][HH][12];    // per-warp layer-1 jets (pad 12)

    const int tid = threadIdx.x;
    for (int idx = tid; idx < HH * HH; idx += THREADS)
        sW2[idx >> 6][idx & 63] = W2[idx];
    if (tid < HH) {
        sB2[tid] = b2[tid];
        sW3[tid] = W3[tid];
        float a = W1[tid];          // W1[0][j]  (coeff of phi)
        float b = W1[HH + tid];     // W1[1][j]  (coeff of theta)
        sL1[tid][0] = a;       sL1[tid][1] = b;
        sL1[tid][2] = a * a;   sL1[tid][3] = a * b;     sL1[tid][4] = b * b;
        sL1[tid][5] = a * a * a; sL1[tid][6] = a * a * b;
        sL1[tid][7] = a * b * b; sL1[tid][8] = b * b * b;
        sL1[tid][9] = b1[tid];
        sL1[tid][10] = 0.0f; sL1[tid][11] = 0.0f;
    }
    __syncthreads();

    const int lane = tid & 31;
    const int w    = tid >> 5;
    const int gw   = blockIdx.x * WARPS_PER_BLOCK + w;
    const int nwarps = gridDim.x * WARPS_PER_BLOCK;

    for (int i = gw; i < n; i += nwarps) {
        const float p = phi[i];
        const float t = theta[i];

        // ---- Phase 1: layer-1 jets (lane handles units lane and lane+32) ----
        #pragma unroll
        for (int u = 0; u < 2; ++u) {
            const int j = lane + 32 * u;
            const float4* lp = (const float4*)sL1[j];
            const float4 l0 = lp[0];                         // a, b, aa, ab
            const float4 l1 = lp[1];                         // bb, aaa, aab, abb
            const float2 l2 = *(const float2*)&sL1[j][8];    // bbb, b1
            const float z = fmaf(l0.x, p, fmaf(l0.y, t, l2.y));
            float f, f1, f2, f3;
            tanh_derivs(z, f, f1, f2, f3);
            float4* vp = (float4*)sV[w][j];
            vp[0] = make_float4(f, f1 * l0.x, f1 * l0.y, f2 * l0.z);
            vp[1] = make_float4(f2 * l0.w, f2 * l1.x, f3 * l1.y, f3 * l1.z);
            *(float2*)&sV[w][j][8] = make_float2(f3 * l1.w, f3 * l2.x);
        }
        __syncwarp();

        // ---- Phase 2: z2 jets for units (lane) and (lane+32) ----
        float z0[10], z1[10];
        #pragma unroll
        for (int cc = 0; cc < 10; ++cc) { z0[cc] = 0.0f; z1[cc] = 0.0f; }
        z0[0] = sB2[lane];
        z1[0] = sB2[lane + 32];

        #pragma unroll 4
        for (int j = 0; j < HH; ++j) {
            const float4* vp = (const float4*)sV[w][j];
            const float4 va = vp[0];
            const float4 vb = vp[1];
            const float2 vc = *(const float2*)&sV[w][j][8];
            const float w0 = sW2[j][lane];
            const float w1 = sW2[j][lane + 32];
            z0[0] = fmaf(w0, va.x, z0[0]);  z1[0] = fmaf(w1, va.x, z1[0]);
            z0[1] = fmaf(w0, va.y, z0[1]);  z1[1] = fmaf(w1, va.y, z1[1]);
            z0[2] = fmaf(w0, va.z, z0[2]);  z1[2] = fmaf(w1, va.z, z1[2]);
            z0[3] = fmaf(w0, va.w, z0[3]);  z1[3] = fmaf(w1, va.w, z1[3]);
            z0[4] = fmaf(w0, vb.x, z0[4]);  z1[4] = fmaf(w1, vb.x, z1[4]);
            z0[5] = fmaf(w0, vb.y, z0[5]);  z1[5] = fmaf(w1, vb.y, z1[5]);
            z0[6] = fmaf(w0, vb.z, z0[6]);  z1[6] = fmaf(w1, vb.z, z1[6]);
            z0[7] = fmaf(w0, vb.w, z0[7]);  z1[7] = fmaf(w1, vb.w, z1[7]);
            z0[8] = fmaf(w0, vc.x, z0[8]);  z1[8] = fmaf(w1, vc.x, z1[8]);
            z0[9] = fmaf(w0, vc.y, z0[9]);  z1[9] = fmaf(w1, vc.y, z1[9]);
        }
        __syncwarp();   // sV consumed; safe to overwrite next iteration

        // ---- Phase 3: tanh-compose, weight by W3, warp reduce T-jet ----
        float acc[10];
        #pragma unroll
        for (int cc = 0; cc < 10; ++cc) acc[cc] = 0.0f;
        compose_acc(z0, sW3[lane], acc);
        compose_acc(z1, sW3[lane + 32], acc);

        #pragma unroll
        for (int cc = 0; cc < 10; ++cc) {
            float v = acc[cc];
            #pragma unroll
            for (int off = 16; off; off >>= 1)
                v += __shfl_xor_sync(0xffffffffu, v, off);
            acc[cc] = v;
        }

        if (lane == 0) {
            const float Tp = acc[1], Tt = acc[2];
            const float Tpp = acc[3], Tpt = acc[4], Ttt = acc[5];
            const float Tppp = acc[6], Tppt = acc[7], Tptt = acc[8], Tttt = acc[9];

            float s, cn;
            sincosf(t, &s, &cn);
            const float r    = radius[i];
            const float invs = 1.0f / s;
            const float invr = 1.0f / r;

            const float ut = fmaf(Tp, invs, Tt);
            const float up = fmaf(Tp, invs, -Tt);

            // u_theta_theta = d/dt[-u_th*s] = -(Tpt + c*Tt + s*Ttt)
            const float u_th_t = -(Tpt + cn * Tt + s * Ttt);
            // u_phi_phi = Tpp/s - Tpt
            const float u_ph_p = fmaf(Tpp, invs, -Tpt);
            const float div = (u_th_t + u_ph_p) * invs * invr;

            const float c2s2 = cn * cn - s * s;
            // u_theta_theta_theta
            const float u_th_tt = -(cn * Tpt + s * Tptt + 3.0f * s * cn * Ttt
                                    + c2s2 * Tt + s * s * Tttt);
            // u_theta_phi_phi
            const float u_th_pp = -(fmaf(Tppp, invs, Tppt));
            // u_phi_theta_theta
            const float u_ph_tt = cn * Tpt + s * Tptt - c2s2 * Tt
                                  - 3.0f * s * cn * Ttt - s * s * Tttt;
            // u_phi_phi_phi
            const float u_ph_pp = fmaf(Tppp, invs, -Tppt);

            const float invr2  = invr * invr;
            const float invrs2 = invs * invs * invr2;
            const float lapt = fmaf(s * invr2, u_th_tt, u_th_pp * invrs2);
            const float lapp = fmaf(s * invr2, u_ph_tt, u_ph_pp * invrs2);
            const float comp = s * (lapt * lapt + lapp * lapp);
            const float sv   = -(ut * hth[i] + up * hph[i]) - brr[i] * div;
            const float tg   = div - ut * (s / cn) * invr;

            out[i]         = ut;
            out[n + i]     = up;
            out[2 * n + i] = div;
            out[3 * n + i] = sv;
            out[4 * n + i] = tg;
            out[5 * n + i] = comp;
        }
    }
}

extern "C" void kernel_launch(void* const* d_in, const int* in_sizes, int n_in,
                              void* d_out, int out_size) {
    const float* phi    = (const float*)d_in[0];
    const float* theta  = (const float*)d_in[1];
    const float* radius = (const float*)d_in[2];
    const float* hth    = (const float*)d_in[3];
    const float* hph    = (const float*)d_in[4];
    const float* brr    = (const float*)d_in[5];
    const float* W1     = (const float*)d_in[6];
    const float* b1     = (const float*)d_in[7];
    const float* W2     = (const float*)d_in[8];
    const float* b2     = (const float*)d_in[9];
    const float* W3     = (const float*)d_in[10];
    const float* b3     = (const float*)d_in[11];
    float* out = (float*)d_out;
    const int n = in_sizes[0];

    pinn_flow_kernel<<<GRID_BLOCKS, THREADS>>>(
        phi, theta, radius, hth, hph, brr,
        W1, b1, W2, b2, W3, b3, out, n);
}

// round 2
// speedup vs baseline: 1.0633x; 1.0633x over previous
#include <cuda_runtime.h>
#include <cuda_bf16.h>

#define HH 64
#define WARPS_PER_BLOCK 8
#define THREADS (WARPS_PER_BLOCK * 32)
#define GRID_BLOCKS 2048

typedef unsigned long long u64;

// packed f32x2 fma: (d.lo, d.hi) = (a.lo*b.lo+c.lo, a.hi*b.hi+c.hi)
#define FMA2(d, a, b, c) \
    asm("fma.rn.f32x2 %0, %1, %2, %3;" : "=l"(d) : "l"(a), "l"(b), "l"(c))
#define PACK2(d, lo, hi) \
    asm("mov.b64 %0, {%1, %2};" : "=l"(d) : "f"(lo), "f"(hi))
#define UNPACK2(lo, hi, s) \
    asm("mov.b64 {%0, %1}, %2;" : "=f"(lo), "=f"(hi) : "l"(s))

// tanh and its first three derivatives
__device__ __forceinline__ void tanh_derivs(float z, float& f, float& f1, float& f2, float& f3) {
    f  = tanhf(z);
    f1 = 1.0f - f * f;                 // f'
    f2 = -2.0f * f * f1;               // f''
    f3 = -2.0f * (f1 * f1 + f * f2);   // f'''
}

// Faa di Bruno: h = tanh(z(p,t)) jet composition, accumulate w3 * h-jet into acc.
// jet order: [0]=val [1]=p [2]=t [3]=pp [4]=pt [5]=tt [6]=ppp [7]=ppt [8]=ptt [9]=ttt
__device__ __forceinline__ void compose_acc(const float* z, float w3, float* acc) {
    float f, f1, f2, f3;
    tanh_derivs(z[0], f, f1, f2, f3);
    float zp = z[1], zt = z[2], zpp = z[3], zpt = z[4], ztt = z[5];
    float zppp = z[6], zppt = z[7], zptt = z[8], zttt = z[9];
    acc[0] = fmaf(w3, f, acc[0]);
    acc[1] = fmaf(w3, f1 * zp, acc[1]);
    acc[2] = fmaf(w3, f1 * zt, acc[2]);
    acc[3] = fmaf(w3, fmaf(f2, zp * zp, f1 * zpp), acc[3]);
    acc[4] = fmaf(w3, fmaf(f2, zp * zt, f1 * zpt), acc[4]);
    acc[5] = fmaf(w3, fmaf(f2, zt * zt, f1 * ztt), acc[5]);
    acc[6] = fmaf(w3, f3 * zp * zp * zp + 3.0f * f2 * zp * zpp + f1 * zppp, acc[6]);
    acc[7] = fmaf(w3, f3 * zp * zp * zt + f2 * (zpp * zt + 2.0f * zp * zpt) + f1 * zppt, acc[7]);
    acc[8] = fmaf(w3, f3 * zp * zt * zt + f2 * (ztt * zp + 2.0f * zt * zpt) + f1 * zptt, acc[8]);
    acc[9] = fmaf(w3, f3 * zt * zt * zt + 3.0f * f2 * zt * ztt + f1 * zttt, acc[9]);
}

__global__ __launch_bounds__(THREADS) void pinn_flow_kernel(
    const float* __restrict__ phi, const float* __restrict__ theta,
    const float* __restrict__ radius, const float* __restrict__ hth,
    const float* __restrict__ hph, const float* __restrict__ brr,
    const float* __restrict__ W1, const float* __restrict__ b1,
    const float* __restrict__ W2, const float* __restrict__ b2,
    const float* __restrict__ W3, const float* __restrict__ b3,
    float* __restrict__ out, int n)
{
    // sW2p[j][k] = (W2[j][k], W2[j][k+32]) for k in [0,32): one LDS.64 per j per lane
    __shared__ __align__(16) float2 sW2p[HH][HH / 2];          // 16 KB
    __shared__ __align__(16) float sL1[HH][12];                // a,b,aa,ab,bb,aaa,aab,abb,bbb,b1 (pad 12)
    __shared__ float sB2[HH];
    __shared__ float sW3[HH];
    __shared__ __align__(16) float sV[WARPS_PER_BLOCK][HH][12];// per-warp layer-1 jets (pad 12)

    const int tid = threadIdx.x;
    for (int idx = tid; idx < HH * (HH / 2); idx += THREADS) {
        const int j = idx >> 5;          // row
        const int k = idx & 31;          // paired column
        sW2p[j][k] = make_float2(W2[j * HH + k], W2[j * HH + k + 32]);
    }
    if (tid < HH) {
        sB2[tid] = b2[tid];
        sW3[tid] = W3[tid];
        float a = W1[tid];          // W1[0][j]  (coeff of phi)
        float b = W1[HH + tid];     // W1[1][j]  (coeff of theta)
        sL1[tid][0] = a;       sL1[tid][1] = b;
        sL1[tid][2] = a * a;   sL1[tid][3] = a * b;     sL1[tid][4] = b * b;
        sL1[tid][5] = a * a * a; sL1[tid][6] = a * a * b;
        sL1[tid][7] = a * b * b; sL1[tid][8] = b * b * b;
        sL1[tid][9] = b1[tid];
        sL1[tid][10] = 0.0f; sL1[tid][11] = 0.0f;
    }
    __syncthreads();

    const int lane = tid & 31;
    const int w    = tid >> 5;
    const int gw   = blockIdx.x * WARPS_PER_BLOCK + w;
    const int nwarps = gridDim.x * WARPS_PER_BLOCK;

    for (int i = gw; i < n; i += nwarps) {
        const float p = phi[i];
        const float t = theta[i];

        // ---- Phase 1: layer-1 jets (lane handles units lane and lane+32) ----
        #pragma unroll
        for (int u = 0; u < 2; ++u) {
            const int j = lane + 32 * u;
            const float4* lp = (const float4*)sL1[j];
            const float4 l0 = lp[0];                         // a, b, aa, ab
            const float4 l1 = lp[1];                         // bb, aaa, aab, abb
            const float2 l2 = *(const float2*)&sL1[j][8];    // bbb, b1
            const float z = fmaf(l0.x, p, fmaf(l0.y, t, l2.y));
            float f, f1, f2, f3;
            tanh_derivs(z, f, f1, f2, f3);
            float4* vp = (float4*)sV[w][j];
            vp[0] = make_float4(f, f1 * l0.x, f1 * l0.y, f2 * l0.z);
            vp[1] = make_float4(f2 * l0.w, f2 * l1.x, f3 * l1.y, f3 * l1.z);
            *(float2*)&sV[w][j][8] = make_float2(f3 * l1.w, f3 * l2.x);
        }
        __syncwarp();

        // ---- Phase 2: z2 jets for units (lane) and (lane+32), packed f32x2 ----
        // pair c of unit k holds (z[2c], z[2c+1])
        u64 z0p[5], z1p[5];
        PACK2(z0p[0], sB2[lane], 0.0f);
        PACK2(z1p[0], sB2[lane + 32], 0.0f);
        #pragma unroll
        for (int c = 1; c < 5; ++c) { z0p[c] = 0ULL; z1p[c] = 0ULL; }

        #pragma unroll 4
        for (int j = 0; j < HH; ++j) {
            const ulonglong2 va = *(const ulonglong2*)&sV[w][j][0];   // pairs 0,1
            const ulonglong2 vb = *(const ulonglong2*)&sV[w][j][4];   // pairs 2,3
            const u64        vc = *(const u64*)&sV[w][j][8];          // pair 4
            const float2 wv = sW2p[j][lane];
            u64 wd0, wd1;
            PACK2(wd0, wv.x, wv.x);
            PACK2(wd1, wv.y, wv.y);
            FMA2(z0p[0], wd0, va.x, z0p[0]);  FMA2(z1p[0], wd1, va.x, z1p[0]);
            FMA2(z0p[1], wd0, va.y, z0p[1]);  FMA2(z1p[1], wd1, va.y, z1p[1]);
            FMA2(z0p[2], wd0, vb.x, z0p[2]);  FMA2(z1p[2], wd1, vb.x, z1p[2]);
            FMA2(z0p[3], wd0, vb.y, z0p[3]);  FMA2(z1p[3], wd1, vb.y, z1p[3]);
            FMA2(z0p[4], wd0, vc,   z0p[4]);  FMA2(z1p[4], wd1, vc,   z1p[4]);
        }
        __syncwarp();   // sV consumed; safe to overwrite next iteration

        // ---- Phase 3: unpack, tanh-compose, weight by W3, warp reduce T-jet ----
        float z0[10], z1[10];
        #pragma unroll
        for (int c = 0; c < 5; ++c) {
            UNPACK2(z0[2 * c], z0[2 * c + 1], z0p[c]);
            UNPACK2(z1[2 * c], z1[2 * c + 1], z1p[c]);
        }

        float acc[10];
        #pragma unroll
        for (int cc = 0; cc < 10; ++cc) acc[cc] = 0.0f;
        compose_acc(z0, sW3[lane], acc);
        compose_acc(z1, sW3[lane + 32], acc);

        #pragma unroll
        for (int cc = 0; cc < 10; ++cc) {
            float v = acc[cc];
            #pragma unroll
            for (int off = 16; off; off >>= 1)
                v += __shfl_xor_sync(0xffffffffu, v, off);
            acc[cc] = v;
        }

        if (lane == 0) {
            const float Tp = acc[1], Tt = acc[2];
            const float Tpp = acc[3], Tpt = acc[4], Ttt = acc[5];
            const float Tppp = acc[6], Tppt = acc[7], Tptt = acc[8], Tttt = acc[9];

            float s, cn;
            sincosf(t, &s, &cn);
            const float r    = radius[i];
            const float invs = 1.0f / s;
            const float invr = 1.0f / r;

            const float ut = fmaf(Tp, invs, Tt);
            const float up = fmaf(Tp, invs, -Tt);

            const float u_th_t = -(Tpt + cn * Tt + s * Ttt);
            const float u_ph_p = fmaf(Tpp, invs, -Tpt);
            const float div = (u_th_t + u_ph_p) * invs * invr;

            const float c2s2 = cn * cn - s * s;
            const float u_th_tt = -(cn * Tpt + s * Tptt + 3.0f * s * cn * Ttt
                                    + c2s2 * Tt + s * s * Tttt);
            const float u_th_pp = -(fmaf(Tppp, invs, Tppt));
            const float u_ph_tt = cn * Tpt + s * Tptt - c2s2 * Tt
                                  - 3.0f * s * cn * Ttt - s * s * Tttt;
            const float u_ph_pp = fmaf(Tppp, invs, -Tppt);

            const float invr2  = invr * invr;
            const float invrs2 = invs * invs * invr2;
            const float lapt = fmaf(s * invr2, u_th_tt, u_th_pp * invrs2);
            const float lapp = fmaf(s * invr2, u_ph_tt, u_ph_pp * invrs2);
            const float comp = s * (lapt * lapt + lapp * lapp);
            const float sv   = -(ut * hth[i] + up * hph[i]) - brr[i] * div;
            const float tg   = div - ut * (s / cn) * invr;

            out[i]         = ut;
            out[n + i]     = up;
            out[2 * n + i] = div;
            out[3 * n + i] = sv;
            out[4 * n + i] = tg;
            out[5 * n + i] = comp;
        }
    }
}

extern "C" void kernel_launch(void* const* d_in, const int* in_sizes, int n_in,
                              void* d_out, int out_size) {
    const float* phi    = (const float*)d_in[0];
    const float* theta  = (const float*)d_in[1];
    const float* radius = (const float*)d_in[2];
    const float* hth    = (const float*)d_in[3];
    const float* hph    = (const float*)d_in[4];
    const float* brr    = (const float*)d_in[5];
    const float* W1     = (const float*)d_in[6];
    const float* b1     = (const float*)d_in[7];
    const float* W2     = (const float*)d_in[8];
    const float* b2     = (const float*)d_in[9];
    const float* W3     = (const float*)d_in[10];
    const float* b3     = (const float*)d_in[11];
    float* out = (float*)d_out;
    const int n = in_sizes[0];

    pinn_flow_kernel<<<GRID_BLOCKS, THREADS>>>(
        phi, theta, radius, hth, hph, brr,
        W1, b1, W2, b2, W3, b3, out, n);
}

// round 3
// speedup vs baseline: 1.1107x; 1.0445x over previous
#include <cuda_runtime.h>
#include <cuda_bf16.h>

#define HH 64
#define WARPS_PER_BLOCK 4
#define THREADS (WARPS_PER_BLOCK * 32)
#define GRID_BLOCKS 2048

typedef unsigned long long u64;

// packed f32x2 fma: (d.lo, d.hi) = (a.lo*b.lo+c.lo, a.hi*b.hi+c.hi)
#define FMA2(d, a, b, c) \
    asm("fma.rn.f32x2 %0, %1, %2, %3;" : "=l"(d) : "l"(a), "l"(b), "l"(c))
#define PACK2(d, lo, hi) \
    asm("mov.b64 %0, {%1, %2};" : "=l"(d) : "f"(lo), "f"(hi))
#define UNPACK2(lo, hi, s) \
    asm("mov.b64 {%0, %1}, %2;" : "=f"(lo), "=f"(hi) : "l"(s))

// tanh and its first three derivatives
__device__ __forceinline__ void tanh_derivs(float z, float& f, float& f1, float& f2, float& f3) {
    f  = tanhf(z);
    f1 = 1.0f - f * f;                 // f'
    f2 = -2.0f * f * f1;               // f''
    f3 = -2.0f * (f1 * f1 + f * f2);   // f'''
}

// Faa di Bruno: h = tanh(z(p,t)) jet composition, accumulate w3 * h-jet into acc.
// jet order: [0]=val [1]=p [2]=t [3]=pp [4]=pt [5]=tt [6]=ppp [7]=ppt [8]=ptt [9]=ttt
__device__ __forceinline__ void compose_acc(const float* z, float w3, float* acc) {
    float f, f1, f2, f3;
    tanh_derivs(z[0], f, f1, f2, f3);
    float zp = z[1], zt = z[2], zpp = z[3], zpt = z[4], ztt = z[5];
    float zppp = z[6], zppt = z[7], zptt = z[8], zttt = z[9];
    acc[1] = fmaf(w3, f1 * zp, acc[1]);
    acc[2] = fmaf(w3, f1 * zt, acc[2]);
    acc[3] = fmaf(w3, fmaf(f2, zp * zp, f1 * zpp), acc[3]);
    acc[4] = fmaf(w3, fmaf(f2, zp * zt, f1 * zpt), acc[4]);
    acc[5] = fmaf(w3, fmaf(f2, zt * zt, f1 * ztt), acc[5]);
    acc[6] = fmaf(w3, f3 * zp * zp * zp + 3.0f * f2 * zp * zpp + f1 * zppp, acc[6]);
    acc[7] = fmaf(w3, f3 * zp * zp * zt + f2 * (zpp * zt + 2.0f * zp * zpt) + f1 * zppt, acc[7]);
    acc[8] = fmaf(w3, f3 * zp * zt * zt + f2 * (ztt * zp + 2.0f * zt * zpt) + f1 * zptt, acc[8]);
    acc[9] = fmaf(w3, f3 * zt * zt * zt + 3.0f * f2 * zt * ztt + f1 * zttt, acc[9]);
}

__global__ __launch_bounds__(THREADS) void pinn_flow_kernel(
    const float* __restrict__ phi, const float* __restrict__ theta,
    const float* __restrict__ radius, const float* __restrict__ hth,
    const float* __restrict__ hph, const float* __restrict__ brr,
    const float* __restrict__ W1, const float* __restrict__ b1,
    const float* __restrict__ W2, const float* __restrict__ b2,
    const float* __restrict__ W3, const float* __restrict__ b3,
    float* __restrict__ out, int n)
{
    // sW2q[j][hl] = (W2[j][hl], W2[j][hl+16], W2[j][hl+32], W2[j][hl+48])
    __shared__ __align__(16) float4 sW2q[HH][16];                 // 16 KB
    __shared__ __align__(16) float  sL1[HH][12];                  // a,b,aa,ab,bb,aaa,aab,abb,bbb,b1
    __shared__ float sB2[HH];
    __shared__ float sW3[HH];
    // per-warp, per-j: point A jet (words 0-11), point B jet (words 12-23)
    __shared__ __align__(16) float sV[WARPS_PER_BLOCK][HH][24];   // 24 KB

    const int tid = threadIdx.x;
    for (int idx = tid; idx < HH * 16; idx += THREADS) {
        const int j  = idx >> 4;
        const int hl = idx & 15;
        sW2q[j][hl] = make_float4(W2[j * HH + hl],      W2[j * HH + hl + 16],
                                  W2[j * HH + hl + 32], W2[j * HH + hl + 48]);
    }
    if (tid < HH) {
        sB2[tid] = b2[tid];
        sW3[tid] = W3[tid];
        float a = W1[tid];          // W1[0][j]  (coeff of phi)
        float b = W1[HH + tid];     // W1[1][j]  (coeff of theta)
        sL1[tid][0] = a;       sL1[tid][1] = b;
        sL1[tid][2] = a * a;   sL1[tid][3] = a * b;     sL1[tid][4] = b * b;
        sL1[tid][5] = a * a * a; sL1[tid][6] = a * a * b;
        sL1[tid][7] = a * b * b; sL1[tid][8] = b * b * b;
        sL1[tid][9] = b1[tid];
        sL1[tid][10] = 0.0f; sL1[tid][11] = 0.0f;
    }
    __syncthreads();

    const int lane = tid & 31;
    const int w    = tid >> 5;
    const int half = lane >> 4;          // 0 = point A, 1 = point B
    const int hl   = lane & 15;
    const int gw   = blockIdx.x * WARPS_PER_BLOCK + w;
    const int nwarps = gridDim.x * WARPS_PER_BLOCK;
    const int ntasks = (n + 1) >> 1;     // 2 points per warp-task

    for (int task = gw; task < ntasks; task += nwarps) {
        const int i = 2 * task + half;           // this half-warp's point
        const int iL = (i < n) ? i : (n - 1);    // clamped for loads
        const float p = phi[iL];
        const float t = theta[iL];

        // ---- Phase 1: layer-1 jets; lane computes units hl+16u for its point ----
        #pragma unroll
        for (int u = 0; u < 4; ++u) {
            const int j = hl + 16 * u;
            const float4* lp = (const float4*)sL1[j];
            const float4 l0 = lp[0];                         // a, b, aa, ab
            const float4 l1 = lp[1];                         // bb, aaa, aab, abb
            const float2 l2 = *(const float2*)&sL1[j][8];    // bbb, b1
            const float z = fmaf(l0.x, p, fmaf(l0.y, t, l2.y));
            float f, f1, f2, f3;
            tanh_derivs(z, f, f1, f2, f3);
            float* vrow = &sV[w][j][half * 12];
            *(float4*)&vrow[0] = make_float4(f, f1 * l0.x, f1 * l0.y, f2 * l0.z);
            *(float4*)&vrow[4] = make_float4(f2 * l0.w, f2 * l1.x, f3 * l1.y, f3 * l1.z);
            *(float2*)&vrow[8] = make_float2(f3 * l1.w, f3 * l2.x);
        }
        __syncwarp();

        // ---- Phase 2: z2 jets for units hl, hl+16, hl+32, hl+48 (packed f32x2) ----
        u64 zp0[5], zp1[5], zp2[5], zp3[5];
        PACK2(zp0[0], sB2[hl],      0.0f);
        PACK2(zp1[0], sB2[hl + 16], 0.0f);
        PACK2(zp2[0], sB2[hl + 32], 0.0f);
        PACK2(zp3[0], sB2[hl + 48], 0.0f);
        #pragma unroll
        for (int c = 1; c < 5; ++c) { zp0[c] = 0ULL; zp1[c] = 0ULL; zp2[c] = 0ULL; zp3[c] = 0ULL; }

        const float* vbase = &sV[w][0][half * 12];
        #pragma unroll 2
        for (int j = 0; j < HH; ++j) {
            const float* vrow = vbase + j * 24;
            const ulonglong2 va = *(const ulonglong2*)&vrow[0];   // pairs 0,1
            const ulonglong2 vb = *(const ulonglong2*)&vrow[4];   // pairs 2,3
            const u64        vc = *(const u64*)&vrow[8];          // pair 4
            const float4 wq = sW2q[j][hl];
            u64 wd0, wd1, wd2, wd3;
            PACK2(wd0, wq.x, wq.x);
            PACK2(wd1, wq.y, wq.y);
            PACK2(wd2, wq.z, wq.z);
            PACK2(wd3, wq.w, wq.w);
            FMA2(zp0[0], wd0, va.x, zp0[0]);  FMA2(zp1[0], wd1, va.x, zp1[0]);
            FMA2(zp2[0], wd2, va.x, zp2[0]);  FMA2(zp3[0], wd3, va.x, zp3[0]);
            FMA2(zp0[1], wd0, va.y, zp0[1]);  FMA2(zp1[1], wd1, va.y, zp1[1]);
            FMA2(zp2[1], wd2, va.y, zp2[1]);  FMA2(zp3[1], wd3, va.y, zp3[1]);
            FMA2(zp0[2], wd0, vb.x, zp0[2]);  FMA2(zp1[2], wd1, vb.x, zp1[2]);
            FMA2(zp2[2], wd2, vb.x, zp2[2]);  FMA2(zp3[2], wd3, vb.x, zp3[2]);
            FMA2(zp0[3], wd0, vb.y, zp0[3]);  FMA2(zp1[3], wd1, vb.y, zp1[3]);
            FMA2(zp2[3], wd2, vb.y, zp2[3]);  FMA2(zp3[3], wd3, vb.y, zp3[3]);
            FMA2(zp0[4], wd0, vc,   zp0[4]);  FMA2(zp1[4], wd1, vc,   zp1[4]);
            FMA2(zp2[4], wd2, vc,   zp2[4]);  FMA2(zp3[4], wd3, vc,   zp3[4]);
        }
        __syncwarp();   // sV consumed; safe to overwrite next task

        // ---- Phase 3: unpack, tanh-compose, weight by W3, reduce over half-warp ----
        float acc[10];
        #pragma unroll
        for (int cc = 0; cc < 10; ++cc) acc[cc] = 0.0f;
        {
            float z[10];
            #pragma unroll
            for (int c = 0; c < 5; ++c) UNPACK2(z[2 * c], z[2 * c + 1], zp0[c]);
            compose_acc(z, sW3[hl], acc);
            #pragma unroll
            for (int c = 0; c < 5; ++c) UNPACK2(z[2 * c], z[2 * c + 1], zp1[c]);
            compose_acc(z, sW3[hl + 16], acc);
            #pragma unroll
            for (int c = 0; c < 5; ++c) UNPACK2(z[2 * c], z[2 * c + 1], zp2[c]);
            compose_acc(z, sW3[hl + 32], acc);
            #pragma unroll
            for (int c = 0; c < 5; ++c) UNPACK2(z[2 * c], z[2 * c + 1], zp3[c]);
            compose_acc(z, sW3[hl + 48], acc);
        }

        #pragma unroll
        for (int cc = 1; cc < 10; ++cc) {
            float v = acc[cc];
            #pragma unroll
            for (int off = 8; off; off >>= 1)
                v += __shfl_xor_sync(0xffffffffu, v, off);
            acc[cc] = v;
        }

        if (hl == 0 && i < n) {
            const float Tp = acc[1], Tt = acc[2];
            const float Tpp = acc[3], Tpt = acc[4], Ttt = acc[5];
            const float Tppp = acc[6], Tppt = acc[7], Tptt = acc[8], Tttt = acc[9];

            float s, cn;
            sincosf(t, &s, &cn);
            const float r    = radius[i];
            const float invs = 1.0f / s;
            const float invr = 1.0f / r;

            const float ut = fmaf(Tp, invs, Tt);
            const float up = fmaf(Tp, invs, -Tt);

            const float u_th_t = -(Tpt + cn * Tt + s * Ttt);
            const float u_ph_p = fmaf(Tpp, invs, -Tpt);
            const float div = (u_th_t + u_ph_p) * invs * invr;

            const float c2s2 = cn * cn - s * s;
            const float u_th_tt = -(cn * Tpt + s * Tptt + 3.0f * s * cn * Ttt
                                    + c2s2 * Tt + s * s * Tttt);
            const float u_th_pp = -(fmaf(Tppp, invs, Tppt));
            const float u_ph_tt = cn * Tpt + s * Tptt - c2s2 * Tt
                                  - 3.0f * s * cn * Ttt - s * s * Tttt;
            const float u_ph_pp = fmaf(Tppp, invs, -Tppt);

            const float invr2  = invr * invr;
            const float invrs2 = invs * invs * invr2;
            const float lapt = fmaf(s * invr2, u_th_tt, u_th_pp * invrs2);
            const float lapp = fmaf(s * invr2, u_ph_tt, u_ph_pp * invrs2);
            const float comp = s * (lapt * lapt + lapp * lapp);
            const float sv   = -(ut * hth[i] + up * hph[i]) - brr[i] * div;
            const float tg   = div - ut * (s / cn) * invr;

            out[i]         = ut;
            out[n + i]     = up;
            out[2 * n + i] = div;
            out[3 * n + i] = sv;
            out[4 * n + i] = tg;
            out[5 * n + i] = comp;
        }
    }
}

extern "C" void kernel_launch(void* const* d_in, const int* in_sizes, int n_in,
                              void* d_out, int out_size) {
    const float* phi    = (const float*)d_in[0];
    const float* theta  = (const float*)d_in[1];
    const float* radius = (const float*)d_in[2];
    const float* hth    = (const float*)d_in[3];
    const float* hph    = (const float*)d_in[4];
    const float* brr    = (const float*)d_in[5];
    const float* W1     = (const float*)d_in[6];
    const float* b1     = (const float*)d_in[7];
    const float* W2     = (const float*)d_in[8];
    const float* b2     = (const float*)d_in[9];
    const float* W3     = (const float*)d_in[10];
    const float* b3     = (const float*)d_in[11];
    float* out = (float*)d_out;
    const int n = in_sizes[0];

    pinn_flow_kernel<<<GRID_BLOCKS, THREADS>>>(
        phi, theta, radius, hth, hph, brr,
        W1, b1, W2, b2, W3, b3, out, n);
}

// round 4
// speedup vs baseline: 1.1643x; 1.0483x over previous
#include <cuda_runtime.h>
#include <cuda_bf16.h>

#define HH 64
#define JCHUNK 32
#define WARPS_PER_BLOCK 4
#define THREADS (WARPS_PER_BLOCK * 32)
#define GRID_BLOCKS 2048

typedef unsigned long long u64;

// packed f32x2 fma: (d.lo, d.hi) = (a.lo*b.lo+c.lo, a.hi*b.hi+c.hi)
#define FMA2(d, a, b, c) \
    asm("fma.rn.f32x2 %0, %1, %2, %3;" : "=l"(d) : "l"(a), "l"(b), "l"(c))
#define PACK2(d, lo, hi) \
    asm("mov.b64 %0, {%1, %2};" : "=l"(d) : "f"(lo), "f"(hi))
#define UNPACK2(lo, hi, s) \
    asm("mov.b64 {%0, %1}, %2;" : "=f"(lo), "=f"(hi) : "l"(s))

// fast tanh + first three derivatives via ex2.approx + rcp.approx
// tanh(x) = 1 - 2/(1+exp(2x));  exp(2x) = 2^(2x*log2(e))
__device__ __forceinline__ void tanh_derivs(float x, float& f, float& f1, float& f2, float& f3) {
    float e, r;
    asm("ex2.approx.f32 %0, %1;" : "=f"(e) : "f"(x * 2.885390081777927f)); // 2*log2(e)
    asm("rcp.approx.f32 %0, %1;" : "=f"(r) : "f"(e + 1.0f));
    f  = fmaf(-2.0f, r, 1.0f);
    f1 = 1.0f - f * f;                 // f'
    f2 = -2.0f * f * f1;               // f''
    f3 = -2.0f * (f1 * f1 + f * f2);   // f'''
}

// Faa di Bruno: h = tanh(z(p,t)) jet composition, accumulate w3 * h-jet into acc.
// jet order: [0]=val [1]=p [2]=t [3]=pp [4]=pt [5]=tt [6]=ppp [7]=ppt [8]=ptt [9]=ttt
__device__ __forceinline__ void compose_acc(const float* z, float w3, float* acc) {
    float f, f1, f2, f3;
    tanh_derivs(z[0], f, f1, f2, f3);
    float zp = z[1], zt = z[2], zpp = z[3], zpt = z[4], ztt = z[5];
    float zppp = z[6], zppt = z[7], zptt = z[8], zttt = z[9];
    acc[1] = fmaf(w3, f1 * zp, acc[1]);
    acc[2] = fmaf(w3, f1 * zt, acc[2]);
    acc[3] = fmaf(w3, fmaf(f2, zp * zp, f1 * zpp), acc[3]);
    acc[4] = fmaf(w3, fmaf(f2, zp * zt, f1 * zpt), acc[4]);
    acc[5] = fmaf(w3, fmaf(f2, zt * zt, f1 * ztt), acc[5]);
    acc[6] = fmaf(w3, f3 * zp * zp * zp + 3.0f * f2 * zp * zpp + f1 * zppp, acc[6]);
    acc[7] = fmaf(w3, f3 * zp * zp * zt + f2 * (zpp * zt + 2.0f * zp * zpt) + f1 * zppt, acc[7]);
    acc[8] = fmaf(w3, f3 * zp * zt * zt + f2 * (ztt * zp + 2.0f * zt * zpt) + f1 * zptt, acc[8]);
    acc[9] = fmaf(w3, f3 * zt * zt * zt + 3.0f * f2 * zt * ztt + f1 * zttt, acc[9]);
}

__global__ __launch_bounds__(THREADS, 6) void pinn_flow_kernel(
    const float* __restrict__ phi, const float* __restrict__ theta,
    const float* __restrict__ radius, const float* __restrict__ hth,
    const float* __restrict__ hph, const float* __restrict__ brr,
    const float* __restrict__ W1, const float* __restrict__ b1,
    const float* __restrict__ W2, const float* __restrict__ b2,
    const float* __restrict__ W3, const float* __restrict__ b3,
    float* __restrict__ out, int n)
{
    // sW2q[j][hl] = (W2[j][hl], W2[j][hl+16], W2[j][hl+32], W2[j][hl+48])
    __shared__ __align__(16) float4 sW2q[HH][16];                    // 16 KB
    __shared__ __align__(16) float  sL1[HH][12];                     // a,b,aa,ab,bb,aaa,aab,abb,bbb,b1
    __shared__ float sB2[HH];
    __shared__ float sW3[HH];
    // per-warp, per-j-in-chunk: point A jet (words 0-11), point B jet (words 12-23)
    __shared__ __align__(16) float sV[WARPS_PER_BLOCK][JCHUNK][24];  // 12 KB

    const int tid = threadIdx.x;
    for (int idx = tid; idx < HH * 16; idx += THREADS) {
        const int j  = idx >> 4;
        const int hl = idx & 15;
        sW2q[j][hl] = make_float4(W2[j * HH + hl],      W2[j * HH + hl + 16],
                                  W2[j * HH + hl + 32], W2[j * HH + hl + 48]);
    }
    if (tid < HH) {
        sB2[tid] = b2[tid];
        sW3[tid] = W3[tid];
        float a = W1[tid];          // W1[0][j]  (coeff of phi)
        float b = W1[HH + tid];     // W1[1][j]  (coeff of theta)
        sL1[tid][0] = a;       sL1[tid][1] = b;
        sL1[tid][2] = a * a;   sL1[tid][3] = a * b;     sL1[tid][4] = b * b;
        sL1[tid][5] = a * a * a; sL1[tid][6] = a * a * b;
        sL1[tid][7] = a * b * b; sL1[tid][8] = b * b * b;
        sL1[tid][9] = b1[tid];
        sL1[tid][10] = 0.0f; sL1[tid][11] = 0.0f;
    }
    __syncthreads();

    const int lane = tid & 31;
    const int w    = tid >> 5;
    const int half = lane >> 4;          // 0 = point A, 1 = point B
    const int hl   = lane & 15;
    const int gw   = blockIdx.x * WARPS_PER_BLOCK + w;
    const int nwarps = gridDim.x * WARPS_PER_BLOCK;
    const int ntasks = (n + 1) >> 1;     // 2 points per warp-task

    for (int task = gw; task < ntasks; task += nwarps) {
        const int i = 2 * task + half;           // this half-warp's point
        const int iL = (i < n) ? i : (n - 1);    // clamped for loads
        const float p = phi[iL];
        const float t = theta[iL];

        u64 zp0[5], zp1[5], zp2[5], zp3[5];
        PACK2(zp0[0], sB2[hl],      0.0f);
        PACK2(zp1[0], sB2[hl + 16], 0.0f);
        PACK2(zp2[0], sB2[hl + 32], 0.0f);
        PACK2(zp3[0], sB2[hl + 48], 0.0f);
        #pragma unroll
        for (int c = 1; c < 5; ++c) { zp0[c] = 0ULL; zp1[c] = 0ULL; zp2[c] = 0ULL; zp3[c] = 0ULL; }

        #pragma unroll
        for (int chunk = 0; chunk < HH / JCHUNK; ++chunk) {
            // ---- Phase 1: layer-1 jets for j in [32*chunk, 32*chunk+32) ----
            #pragma unroll
            for (int u = 0; u < 2; ++u) {
                const int jj = hl + 16 * u;              // index within chunk
                const int j  = JCHUNK * chunk + jj;      // global unit index
                const float4* lp = (const float4*)sL1[j];
                const float4 l0 = lp[0];                         // a, b, aa, ab
                const float4 l1 = lp[1];                         // bb, aaa, aab, abb
                const float2 l2 = *(const float2*)&sL1[j][8];    // bbb, b1
                const float z = fmaf(l0.x, p, fmaf(l0.y, t, l2.y));
                float f, f1, f2, f3;
                tanh_derivs(z, f, f1, f2, f3);
                float* vrow = &sV[w][jj][half * 12];
                *(float4*)&vrow[0] = make_float4(f, f1 * l0.x, f1 * l0.y, f2 * l0.z);
                *(float4*)&vrow[4] = make_float4(f2 * l0.w, f2 * l1.x, f3 * l1.y, f3 * l1.z);
                *(float2*)&vrow[8] = make_float2(f3 * l1.w, f3 * l2.x);
            }
            __syncwarp();

            // ---- Phase 2: accumulate z2 jets over this chunk's j ----
            const float* vbase = &sV[w][0][half * 12];
            #pragma unroll 2
            for (int jj = 0; jj < JCHUNK; ++jj) {
                const int j = JCHUNK * chunk + jj;
                const float* vrow = vbase + jj * 24;
                const ulonglong2 va = *(const ulonglong2*)&vrow[0];   // pairs 0,1
                const ulonglong2 vb = *(const ulonglong2*)&vrow[4];   // pairs 2,3
                const u64        vc = *(const u64*)&vrow[8];          // pair 4
                const float4 wq = sW2q[j][hl];
                u64 wd0, wd1, wd2, wd3;
                PACK2(wd0, wq.x, wq.x);
                PACK2(wd1, wq.y, wq.y);
                PACK2(wd2, wq.z, wq.z);
                PACK2(wd3, wq.w, wq.w);
                FMA2(zp0[0], wd0, va.x, zp0[0]);  FMA2(zp1[0], wd1, va.x, zp1[0]);
                FMA2(zp2[0], wd2, va.x, zp2[0]);  FMA2(zp3[0], wd3, va.x, zp3[0]);
                FMA2(zp0[1], wd0, va.y, zp0[1]);  FMA2(zp1[1], wd1, va.y, zp1[1]);
                FMA2(zp2[1], wd2, va.y, zp2[1]);  FMA2(zp3[1], wd3, va.y, zp3[1]);
                FMA2(zp0[2], wd0, vb.x, zp0[2]);  FMA2(zp1[2], wd1, vb.x, zp1[2]);
                FMA2(zp2[2], wd2, vb.x, zp2[2]);  FMA2(zp3[2], wd3, vb.x, zp3[2]);
                FMA2(zp0[3], wd0, vb.y, zp0[3]);  FMA2(zp1[3], wd1, vb.y, zp1[3]);
                FMA2(zp2[3], wd2, vb.y, zp2[3]);  FMA2(zp3[3], wd3, vb.y, zp3[3]);
                FMA2(zp0[4], wd0, vc,   zp0[4]);  FMA2(zp1[4], wd1, vc,   zp1[4]);
                FMA2(zp2[4], wd2, vc,   zp2[4]);  FMA2(zp3[4], wd3, vc,   zp3[4]);
            }
            __syncwarp();   // chunk's sV consumed; safe to overwrite
        }

        // ---- Phase 3: unpack, tanh-compose, weight by W3, reduce over half-warp ----
        float acc[10];
        #pragma unroll
        for (int cc = 0; cc < 10; ++cc) acc[cc] = 0.0f;
        {
            float z[10];
            #pragma unroll
            for (int c = 0; c < 5; ++c) UNPACK2(z[2 * c], z[2 * c + 1], zp0[c]);
            compose_acc(z, sW3[hl], acc);
            #pragma unroll
            for (int c = 0; c < 5; ++c) UNPACK2(z[2 * c], z[2 * c + 1], zp1[c]);
            compose_acc(z, sW3[hl + 16], acc);
            #pragma unroll
            for (int c = 0; c < 5; ++c) UNPACK2(z[2 * c], z[2 * c + 1], zp2[c]);
            compose_acc(z, sW3[hl + 32], acc);
            #pragma unroll
            for (int c = 0; c < 5; ++c) UNPACK2(z[2 * c], z[2 * c + 1], zp3[c]);
            compose_acc(z, sW3[hl + 48], acc);
        }

        #pragma unroll
        for (int cc = 1; cc < 10; ++cc) {
            float v = acc[cc];
            #pragma unroll
            for (int off = 8; off; off >>= 1)
                v += __shfl_xor_sync(0xffffffffu, v, off);
            acc[cc] = v;
        }

        if (hl == 0 && i < n) {
            const float Tp = acc[1], Tt = acc[2];
            const float Tpp = acc[3], Tpt = acc[4], Ttt = acc[5];
            const float Tppp = acc[6], Tppt = acc[7], Tptt = acc[8], Tttt = acc[9];

            float s, cn;
            sincosf(t, &s, &cn);
            const float r    = radius[i];
            const float invs = 1.0f / s;
            const float invr = 1.0f / r;

            const float ut = fmaf(Tp, invs, Tt);
            const float up = fmaf(Tp, invs, -Tt);

            const float u_th_t = -(Tpt + cn * Tt + s * Ttt);
            const float u_ph_p = fmaf(Tpp, invs, -Tpt);
            const float div = (u_th_t + u_ph_p) * invs * invr;

            const float c2s2 = cn * cn - s * s;
            const float u_th_tt = -(cn * Tpt + s * Tptt + 3.0f * s * cn * Ttt
                                    + c2s2 * Tt + s * s * Tttt);
            const float u_th_pp = -(fmaf(Tppp, invs, Tppt));
            const float u_ph_tt = cn * Tpt + s * Tptt - c2s2 * Tt
                                  - 3.0f * s * cn * Ttt - s * s * Tttt;
            const float u_ph_pp = fmaf(Tppp, invs, -Tppt);

            const float invr2  = invr * invr;
            const float invrs2 = invs * invs * invr2;
            const float lapt = fmaf(s * invr2, u_th_tt, u_th_pp * invrs2);
            const float lapp = fmaf(s * invr2, u_ph_tt, u_ph_pp * invrs2);
            const float comp = s * (lapt * lapt + lapp * lapp);
            const float sv   = -(ut * hth[i] + up * hph[i]) - brr[i] * div;
            const float tg   = div - ut * (s / cn) * invr;

            out[i]         = ut;
            out[n + i]     = up;
            out[2 * n + i] = div;
            out[3 * n + i] = sv;
            out[4 * n + i] = tg;
            out[5 * n + i] = comp;
        }
    }
}

extern "C" void kernel_launch(void* const* d_in, const int* in_sizes, int n_in,
                              void* d_out, int out_size) {
    const float* phi    = (const float*)d_in[0];
    const float* theta  = (const float*)d_in[1];
    const float* radius = (const float*)d_in[2];
    const float* hth    = (const float*)d_in[3];
    const float* hph    = (const float*)d_in[4];
    const float* brr    = (const float*)d_in[5];
    const float* W1     = (const float*)d_in[6];
    const float* b1     = (const float*)d_in[7];
    const float* W2     = (const float*)d_in[8];
    const float* b2     = (const float*)d_in[9];
    const float* W3     = (const float*)d_in[10];
    const float* b3     = (const float*)d_in[11];
    float* out = (float*)d_out;
    const int n = in_sizes[0];

    pinn_flow_kernel<<<GRID_BLOCKS, THREADS>>>(
        phi, theta, radius, hth, hph, brr,
        W1, b1, W2, b2, W3, b3, out, n);
}